// round 2
// baseline (speedup 1.0000x reference)
#include <cuda_runtime.h>

#define WARM_UP   365
#define LENF      15
#define N_PHY     12
#define NMUL      4
#define NEARZERO_F 1e-5f

#define T_FIX 2000
#define G_FIX 4000
#define CH    105           // conv chunk; multiple of 15 so ring slots are compile-time

// scratch: q summed over the 4 multipliers, per (t, g); and per-gauge conv weights
__device__ float g_qs[T_FIX * G_FIX];     // 32 MB
__device__ float g_w[LENF * G_FIX];

// ---------------------------------------------------------------------------
// Kernel A: routing weights (gamma kernel). Gamma(aa)*th^aa cancels in the
// normalization; the 1/NMUL mean factor is folded in here.
// ---------------------------------------------------------------------------
__global__ void weights_kernel(const float* __restrict__ par, int G) {
    int g = blockIdx.x * blockDim.x + threadIdx.x;
    if (g >= G) return;
    const float* pg = par + g * (N_PHY * NMUL + 2);
    float a  = pg[N_PHY * NMUL + 0] * 2.9f;
    float b  = pg[N_PHY * NMUL + 1] * 6.5f;
    float aa = fmaxf(a, 0.0f) + 0.1f;
    float th = fmaxf(b, 0.0f) + 0.5f;
    float w[LENF];
    float s = 0.0f;
#pragma unroll
    for (int k = 0; k < LENF; k++) {
        float tg = (float)k + 0.5f;
        float u  = powf(tg, aa - 1.0f) * expf(-tg / th);
        w[k] = u;
        s += u;
    }
    float inv = 0.25f / s;   // 0.25 = mean over NMUL=4
#pragma unroll
    for (int k = 0; k < LENF; k++) g_w[k * G + g] = w[k] * inv;
}

// ---------------------------------------------------------------------------
// Kernel B: the serial HBV recurrence. One thread = one gauge = 4 independent
// multiplier chains (4-way ILP per thread). 4000 threads = 125 warps, one
// warp per SM; issue-bound.
// ---------------------------------------------------------------------------
__global__ __launch_bounds__(32)
void hbv_kernel(const float* __restrict__ x,    // [T, G, 3]
                const float* __restrict__ par,  // [1, G, 50]
                int T, int G) {
    int g = blockIdx.x * 32 + threadIdx.x;
    if (g >= G) return;

    const float* pg = par + g * (N_PHY * NMUL + 2);

    float beta[4], invfc[4], fc[4], k0c[4], k1c[4], omk1[4], k2c[4], omk2[4],
          percv[4], uzlv[4], cfm[4], cfmtt[4], cfrv[4], cwhv[4], invlpfc[4];
#pragma unroll
    for (int m = 0; m < 4; m++) {
        float r0  = pg[0*4+m],  r1  = pg[1*4+m],  r2  = pg[2*4+m];
        float r3  = pg[3*4+m],  r4  = pg[4*4+m],  r5  = pg[5*4+m];
        float r6  = pg[6*4+m],  r7  = pg[7*4+m],  r8  = pg[8*4+m];
        float r9  = pg[9*4+m],  r10 = pg[10*4+m], r11 = pg[11*4+m];
        beta[m] = 1.0f + r0 * 5.0f;
        float fcv = 50.0f + r1 * 950.0f;
        fc[m] = fcv; invfc[m] = 1.0f / fcv;
        k0c[m] = 0.05f + r2 * 0.85f;
        float k1v = 0.01f + r3 * 0.49f;   k1c[m] = k1v; omk1[m] = 1.0f - k1v;
        float k2v = 0.001f + r4 * 0.199f; k2c[m] = k2v; omk2[m] = 1.0f - k2v;
        float lp = 0.2f + r5 * 0.8f;
        invlpfc[m] = 1.0f / (lp * fcv);
        percv[m] = r6 * 10.0f;
        uzlv[m]  = r7 * 100.0f;
        float ttv = -2.5f + r8 * 5.0f;
        float cf  = 0.5f + r9 * 9.5f;
        cfm[m] = cf; cfmtt[m] = cf * ttv;
        cfrv[m] = r10 * 0.1f;
        cwhv[m] = r11 * 0.2f;
    }

    float sp[4], mw[4], sm[4], suz[4], slz[4];
#pragma unroll
    for (int m = 0; m < 4; m++) { sp[m]=0.001f; mw[m]=0.001f; sm[m]=0.001f; suz[m]=0.001f; slz[m]=0.001f; }

    const int stride = G * 3;
    const float* xp = x + g * 3;          // forcing for this gauge at t=0
    const float* pf = xp + 4 * stride;    // prefetch pointer (t+4)
    float* qp = g_qs + g;                 // output q pointer

    // prefetch ring, depth 4
    float bP[4], bT[4], bE[4];
#pragma unroll
    for (int k = 0; k < 4; k++) {
        const float* p = xp + k * stride;
        bP[k] = __ldg(p + 0); bT[k] = __ldg(p + 1); bE[k] = __ldg(p + 2);
    }

    for (int tb = 0; tb < T; tb += 4) {
#pragma unroll
        for (int k = 0; k < 4; k++) {
            const int t = tb + k;
            const float P  = bP[k];
            const float Tt = bT[k];
            const float PE = bE[k];

            // prefetch t+4
            if (t + 4 < T) {
                bP[k] = __ldg(pf + 0); bT[k] = __ldg(pf + 1); bE[k] = __ldg(pf + 2);
            }
            pf += stride;

            float qsum = 0.0f;
#pragma unroll
            for (int m = 0; m < 4; m++) {
                // d >= 0  <=>  Tt >= tt (cfmax > 0); shared predicate for rain & melt
                const float d    = fmaf(cfm[m], Tt, -cfmtt[m]);
                const bool  wet  = (d >= 0.0f);
                const float rain = wet ? P : 0.0f;
                const float snow = P - rain;

                // snow <-> meltwater transfer (melt and refreeze are exclusive)
                const float sp1 = sp[m] + snow;
                const float net = wet ? fminf(d, sp1)
                                      : fmaxf(cfrv[m] * d, -mw[m]);
                const float sp2 = sp1 - net;
                const float mw2 = mw[m] + net;
                const float tos = fmaxf(fmaf(-cwhv[m], sp2, mw2), 0.0f);
                mw[m] = mw2 - tos;
                sp[m] = sp2;

                // soil moisture
                const float sw   = fminf(__powf(sm[m] * invfc[m], beta[m]), 1.0f);
                const float rt   = rain + tos;
                const float smrt = sm[m] + rt;
                const float sm2  = fmaf(-rt, sw, smrt);       // sm + rt - rt*sw
                const float sm3  = fminf(sm2, fc[m]);         // after excess removal
                const float re   = smrt - sm3;                // recharge + excess (exact)
                const float omc  = fmaf(-PE, invlpfc[m], 1.0f);
                sm[m] = fmaxf(fmaxf(sm3 - PE, sm3 * omc), NEARZERO_F);

                // upper / lower zones
                const float suz2 = suz[m] + re;
                const float prc  = fminf(suz2, percv[m]);
                const float suz3 = suz2 - prc;
                const float q0   = k0c[m] * fmaxf(suz3 - uzlv[m], 0.0f);
                const float suz4 = suz3 - q0;
                suz[m] = omk1[m] * suz4;
                const float slz2 = slz[m] + prc;
                slz[m] = omk2[m] * slz2;

                qsum += fmaf(k2c[m], slz2, fmaf(k1c[m], suz4, q0));
            }
            *qp = qsum;          // coalesced across the warp
            qp += G;
        }
    }
}

// ---------------------------------------------------------------------------
// Kernel C: per-gauge 15-tap FIR over time, chunked; ring slots are
// compile-time because WARM_UP % 15 == 5 and CH % 15 == 0.
// ---------------------------------------------------------------------------
__global__ void conv_kernel(float* __restrict__ out, int T, int G) {
    int g = blockIdx.x * blockDim.x + threadIdx.x;
    if (g >= G) return;
    int t0 = WARM_UP + (int)blockIdx.y * CH;
    if (t0 >= T) return;

    float w[LENF];
#pragma unroll
    for (int k = 0; k < LENF; k++) w[k] = g_w[k * G + g];

    // ring[tau % 15] = q[tau]; preload q[t0-14 .. t0-1]
    float ring[LENF];
#pragma unroll
    for (int i = 0; i < 14; i++) {
        // (t0 - 14 + i) % 15 == (i + 6) % 15   since t0 % 15 == 5
        ring[(i + 6) % 15] = g_qs[(t0 - 14 + i) * G + g];
    }

    int tb = t0;
    for (int b = 0; b < CH / 15; b++) {
#pragma unroll
        for (int u = 0; u < 15; u++) {
            int t = tb + u;
            if (t < T) {
                ring[(5 + u) % 15] = g_qs[t * G + g];   // t % 15 == (5+u) % 15
                float acc = 0.0f;
#pragma unroll
                for (int k = 0; k < LENF; k++)
                    acc = fmaf(w[k], ring[(5 + u - k + 30) % 15], acc);
                out[(t - WARM_UP) * G + g] = acc;
            }
        }
        tb += 15;
    }
}

// ---------------------------------------------------------------------------
extern "C" void kernel_launch(void* const* d_in, const int* in_sizes, int n_in,
                              void* d_out, int out_size) {
    const float* x   = (const float*)d_in[0];   // [T, G, 3]
    const float* par = (const float*)d_in[1];   // [1, G, 50]
    float* out = (float*)d_out;                 // [T-365, G, 1]

    const int G = in_sizes[1] / (N_PHY * NMUL + 2);
    const int T = in_sizes[0] / (3 * G);

    weights_kernel<<<(G + 127) / 128, 128>>>(par, G);

    hbv_kernel<<<(G + 31) / 32, 32>>>(x, par, T, G);

    const int nchunks = (T - WARM_UP + CH - 1) / CH;
    dim3 cgrid((G + 127) / 128, nchunks);
    conv_kernel<<<cgrid, 128>>>(out, T, G);
}